// round 1
// baseline (speedup 1.0000x reference)
#include <cuda_runtime.h>
#include <math.h>

#define DIRS_PER_THREAD 4
#define BLOCK_THREADS 256
#define MAX_COMP 128

__device__ __forceinline__ float ex2_approx(float x) {
    float r;
    asm("ex2.approx.ftz.f32 %0, %1;" : "=f"(r) : "f"(x));
    return r;
}

__global__ void __launch_bounds__(BLOCK_THREADS)
vmf_mixture_kernel(const float* __restrict__ lambdas,
                   const float* __restrict__ kappas,
                   const float* __restrict__ thetas,
                   const float* __restrict__ phis,
                   const float* __restrict__ wi,
                   float* __restrict__ out,
                   int S, int N)
{
    __shared__ float4 sAB[MAX_COMP];  // {a*mux, a*muy, a*muz, -a}
    __shared__ float  sC[MAX_COMP];   // lambda * norm(kappa)

    int t = threadIdx.x;
    if (t < N) {
        float kappa = kappas[t];
        float lam   = lambdas[t];
        float th    = thetas[t];
        float ph    = phis[t];

        float st = sinf(th), ct = cosf(th);
        float sp = sinf(ph), cp = cosf(ph);

        // normalization: kappa/(2pi(1-exp(-2k))), -> 1/4pi as kappa -> 0
        float k = fmaxf(kappa, 1e-8f);
        float norm;
        if (kappa < 1e-5f) {
            norm = 0.07957747154594767f;           // 1/(4pi)
        } else {
            norm = k * 0.15915494309189535f / (1.0f - expf(-2.0f * k));
        }

        const float LOG2E = 1.4426950408889634f;
        float a = kappa * LOG2E;
        sAB[t] = make_float4(a * (st * cp), a * (st * sp), a * ct, -a);
        sC[t]  = lam * norm;
    }
    __syncthreads();

    int base = blockIdx.x * (BLOCK_THREADS * DIRS_PER_THREAD) + t;

    float x[DIRS_PER_THREAD], y[DIRS_PER_THREAD], z[DIRS_PER_THREAD];
    float acc[DIRS_PER_THREAD];

    #pragma unroll
    for (int j = 0; j < DIRS_PER_THREAD; j++) {
        int idx = base + j * BLOCK_THREADS;
        bool ok = (idx < S);
        int i3 = ok ? (3 * idx) : 0;
        x[j] = wi[i3 + 0];
        y[j] = wi[i3 + 1];
        z[j] = wi[i3 + 2];
        acc[j] = 0.0f;
    }

    #pragma unroll 8
    for (int n = 0; n < N; n++) {
        float4 ab = sAB[n];
        float  c  = sC[n];
        #pragma unroll
        for (int j = 0; j < DIRS_PER_THREAD; j++) {
            float arg = fmaf(ab.x, x[j], ab.w);
            arg = fmaf(ab.y, y[j], arg);
            arg = fmaf(ab.z, z[j], arg);
            acc[j] = fmaf(c, ex2_approx(arg), acc[j]);
        }
    }

    #pragma unroll
    for (int j = 0; j < DIRS_PER_THREAD; j++) {
        int idx = base + j * BLOCK_THREADS;
        if (idx < S) out[idx] = acc[j];
    }
}

extern "C" void kernel_launch(void* const* d_in, const int* in_sizes, int n_in,
                              void* d_out, int out_size)
{
    const float* lambdas = (const float*)d_in[0];
    const float* kappas  = (const float*)d_in[1];
    const float* thetas  = (const float*)d_in[2];
    const float* phis    = (const float*)d_in[3];
    const float* wi      = (const float*)d_in[4];
    float* out = (float*)d_out;

    int N = in_sizes[0];
    int S = in_sizes[4] / 3;

    int per_block = BLOCK_THREADS * DIRS_PER_THREAD;
    int blocks = (S + per_block - 1) / per_block;

    vmf_mixture_kernel<<<blocks, BLOCK_THREADS>>>(lambdas, kappas, thetas, phis, wi,
                                                  out, S, N);
}